// round 9
// baseline (speedup 1.0000x reference)
#include <cuda_runtime.h>
#include <math.h>

#define NB      32
#define NV      256
#define FX      64
#define FYH     33
#define NBINS   (FX*FYH)     // 2112
#define NUFT_DIM (NBINS*2)   // 4224
#define HID     1024
#define OUTD    512

#define EPARTS  4
#define EPN     (NV/EPARTS)  // 64

#define YQ      18           // y-pair slots (y 0..35; valid y < 33)
#define P1K     82           // pass1 jobs per (b,n): 64 cx + 18 cyp

#define S1      64
#define KC1     66
#define KC1P    68
#define S2      64
#define KC2     16

typedef unsigned long long ull;

// -------- device scratch --------
__device__ float4 g_cx4[NB][NV][FX];   // (c, c, -s, -s) of e^{-i pi kx vx}
__device__ float4 g_cxw[NB][NV][FX];   // (sx, pi*vy, Cscaled, 0)
__device__ float4 g_cyp[NB][NV][YQ];   // (re0, re1, im0, im1) of e^{-i pi y vy}
__device__ float  g_f2T[EPARTS][NUFT_DIM][NB];
__device__ float  g_featT[NUFT_DIM][NB];
__device__ float  g_hT[HID][NB];
__device__ float  g_p1[S1][NB][HID];
__device__ float  g_p2[S2][NB][OUTD];

__device__ __forceinline__ float frcp(float x) {
    float r; asm("rcp.approx.ftz.f32 %0, %1;" : "=f"(r) : "f"(x)); return r;
}
__device__ __forceinline__ ull mul2(ull a, ull b){ ull d; asm("mul.rn.f32x2 %0,%1,%2;":"=l"(d):"l"(a),"l"(b)); return d; }
__device__ __forceinline__ ull add2(ull a, ull b){ ull d; asm("add.rn.f32x2 %0,%1,%2;":"=l"(d):"l"(a),"l"(b)); return d; }
__device__ __forceinline__ ull ffma2(ull a, ull b, ull c){ ull d; asm("fma.rn.f32x2 %0,%1,%2,%3;":"=l"(d):"l"(a),"l"(b),"l"(c)); return d; }
__device__ __forceinline__ ull mk2(float lo, float hi){ ull d; asm("mov.b64 %0,{%1,%2};":"=l"(d):"f"(lo),"f"(hi)); return d; }
__device__ __forceinline__ void un2(ull d, float&a, float&b){ asm("mov.b64 {%0,%1},%2;":"=f"(a),"=f"(b):"l"(d)); }

__device__ __forceinline__ ull pack2(float w) {
    unsigned int u = __float_as_uint(w);
    ull d; asm("mov.b64 %0, {%1, %1};" : "=l"(d) : "r"(u)); return d;
}
#define FMA2(d, a, b) asm("fma.rn.f32x2 %0, %1, %2, %0;" : "+l"(d) : "l"(a), "l"(b))
__device__ __forceinline__ void unpack2(ull d, float& lo, float& hi) {
    unsigned int a, b;
    asm("mov.b64 {%0, %1}, %2;" : "=r"(a), "=r"(b) : "l"(d));
    lo = __uint_as_float(a); hi = __uint_as_float(b);
}

// ============================================================
// Pass 1: build packed tables. t -> (b, n, k), k in [0, 82)
// ============================================================
__global__ __launch_bounds__(256) void pass1_kernel(const float* __restrict__ P) {
    int t = blockIdx.x * 256 + threadIdx.x;
    if (t >= NB * NV * P1K) return;
    int bn = t / P1K, k = t - bn * P1K;
    int b = bn >> 8, n = bn & 255;
    const float PI = 3.14159265358979323846f;
    float vx = P[bn * 2], vy = P[bn * 2 + 1];

    if (k < 64) {
        int kk = (k < 32) ? k : k - 64;
        float s = (PI * (float)kk) * vx;
        float sn, cs; sincosf(s, &sn, &cs);
        g_cx4[b][n][k] = make_float4(cs, cs, -sn, -sn);
        int n1 = (n + 1) & 255;
        float wx = P[(b * NV + n1) * 2], wy = P[(b * NV + n1) * 2 + 1];
        float C = -1024.0f * (vx * wy - vy * wx);   // -2048 * 0.5 * area
        g_cxw[b][n][k] = make_float4(s, PI * vy, C, 0.f);
    } else {
        int yq = k - 64;
        int y0 = 2 * yq, y1 = y0 + 1;
        if (y0 >= FYH) y0 = 1;       // pad lanes map to harmless y=1 data
        if (y1 >= FYH) y1 = 1;
        float s0 = (PI * (float)y0) * vy, s1 = (PI * (float)y1) * vy;
        float sn0, cs0, sn1, cs1;
        sincosf(s0, &sn0, &cs0); sincosf(s1, &sn1, &cs1);
        g_cyp[b][n][yq] = make_float4(cs0, cs1, -sn0, -sn1);
    }
}

// reference-exact slow path for a zero denominator
__device__ __noinline__ void slow_S(float sa, float ear, float eai,
                                    float sb, float ebr, float ebi,
                                    float& Sr, float& Si) {
    float dab = sa - sb;
    float den1 = dab * sa;
    float den2 = -dab * sb;
    float den3 = sa * sb;
    Sr = 0.f; Si = 0.f;
    if (den1 != 0.f) { float r = frcp(den1); Sr += ear * r; Si += eai * r; }
    if (den2 != 0.f) { float r = frcp(den2); Sr += ebr * r; Si += ebi * r; }
    if (den3 != 0.f) { float r = frcp(den3); Sr += r; }
}

__device__ __forceinline__ void fb_edge(ull sa2, ull ea_re, ull ea_im,
                                        ull sb2, ull eb_re, ull eb_im,
                                        ull d2, ull nr2, ull ni2, float C,
                                        float aR[2], float aI[2]) {
    float sa[2], sb[2], er[2], ei[2], fr[2], fi[2], dd[2], nr[2], ni[2];
    un2(sa2, sa[0], sa[1]); un2(sb2, sb[0], sb[1]);
    un2(ea_re, er[0], er[1]); un2(ea_im, ei[0], ei[1]);
    un2(eb_re, fr[0], fr[1]); un2(eb_im, fi[0], fi[1]);
    un2(d2, dd[0], dd[1]); un2(nr2, nr[0], nr[1]); un2(ni2, ni[0], ni[1]);
    #pragma unroll
    for (int l = 0; l < 2; l++) {
        float Sr, Si;
        if (dd[l] != 0.f) { float r = frcp(dd[l]); Sr = nr[l] * r; Si = ni[l] * r; }
        else slow_S(sa[l], er[l], ei[l], sb[l], fr[l], fi[l], Sr, Si);
        aR[l] = fmaf(Sr, C, aR[l]);
        aI[l] = fmaf(Si, C, aI[l]);
    }
}

// ============================================================
// Pass 2: thread = (x, y-pair), f32x2 over the two bins
// grid (9, NB, EPARTS), block 128  (idx 0..1151 = 64 x * 18 yq)
// ============================================================
__global__ __launch_bounds__(128) void pass2_kernel() {
    int idx = blockIdx.x * 128 + threadIdx.x;
    int x = idx / YQ, yq = idx - x * YQ;
    int b = blockIdx.y, part = blockIdx.z;
    int n0 = part * EPN;

    float y0f = (float)(2 * yq);
    const float4* cx4b = &g_cx4[b][0][x];    // stride FX float4
    const float4* cxwb = &g_cxw[b][0][x];
    const float4* cypb = &g_cyp[b][0][yq];   // stride YQ float4
    const ull M1 = 0xBF800000BF800000ull;    // (-1, -1)

    // vertex evaluation: sv2, e^{-i sigma} (packed re/im), C
    auto vload = [&](int n, ull& sv2, ull& re2, ull& im2, float& C) {
        ulonglong2 cc = *(const ulonglong2*)(cx4b + n * FX);   // (c,c) (-s,-s)
        ulonglong2 cy = *(const ulonglong2*)(cypb + n * YQ);   // (re0,re1) (im0,im1)
        float4 ww = cxwb[n * FX];
        ull ncxi = mul2(cc.y, M1);
        re2 = ffma2(ncxi, cy.y, mul2(cc.x, cy.x));
        im2 = ffma2(cc.y, cy.x, mul2(cc.x, cy.y));
        C = ww.z;
        float svl = fmaf(y0f, ww.y, ww.x);
        sv2 = mk2(svl, svl + ww.y);
    };

    ull spv, epre, epim; float Cprev;
    {
        int np = (n0 + NV - 1) & (NV - 1);
        vload(np, spv, epre, epim, Cprev);
    }
    ull accR = 0ull, accI = 0ull;

    #pragma unroll 2
    for (int g = 0; g < EPN / 2; g++) {
        int n = n0 + 2 * g;
        ull sv0, re0, im0, sv1, re1, im1; float C0, C1;
        vload(n, sv0, re0, im0, C0);
        vload(n + 1, sv1, re1, im1, C1);

        ull nbre0 = mul2(re0, M1), nbim0 = mul2(im0, M1);
        ull nbre1 = mul2(re1, M1), nbim1 = mul2(im1, M1);

        // edge A: prev -> v0   (sa=spv, ea=ep, sb=sv0, eb=ev0, C=Cprev)
        ull dabA = ffma2(sv0, M1, spv);
        ull dA   = mul2(mul2(dabA, spv), sv0);
        ull nrA  = add2(ffma2(nbre0, spv, mul2(epre, sv0)), dabA);
        ull niA  = ffma2(nbim0, spv, mul2(epim, sv0));
        // edge B: v0 -> v1
        ull dabB = ffma2(sv1, M1, sv0);
        ull dB   = mul2(mul2(dabB, sv0), sv1);
        ull nrB  = add2(ffma2(nbre1, sv0, mul2(re0, sv1)), dabB);
        ull niB  = ffma2(nbim1, sv0, mul2(im0, sv1));

        ull p2 = mul2(dA, dB);
        float pl, ph; un2(p2, pl, ph);
        if (fabsf(pl) > 1e-30f && fabsf(ph) > 1e-30f) {
            ull r2 = mk2(frcp(pl), frcp(ph));
            ull iA = mul2(r2, dB);          // 1/dA
            ull iB = mul2(r2, dA);          // 1/dB
            ull wA = mul2(pack2(Cprev), iA);
            ull wB = mul2(pack2(C0), iB);
            accR = ffma2(nrA, wA, accR); accI = ffma2(niA, wA, accI);
            accR = ffma2(nrB, wB, accR); accI = ffma2(niB, wB, accI);
        } else {
            float aR[2], aI[2];
            un2(accR, aR[0], aR[1]); un2(accI, aI[0], aI[1]);
            fb_edge(spv, epre, epim, sv0, re0, im0, dA, nrA, niA, Cprev, aR, aI);
            fb_edge(sv0, re0, im0, sv1, re1, im1, dB, nrB, niB, C0, aR, aI);
            accR = mk2(aR[0], aR[1]); accI = mk2(aI[0], aI[1]);
        }

        spv = sv1; epre = re1; epim = im1; Cprev = C1;
    }

    float r0, r1, i0, i1;
    un2(accR, r0, r1); un2(accI, i0, i1);
    int y0 = 2 * yq;
    if (y0 < FYH) {
        int bin = x * FYH + y0;
        g_f2T[part][bin * 2][b] = r0;
        g_f2T[part][bin * 2 + 1][b] = i0;
    }
    if (y0 + 1 < FYH) {
        int bin = x * FYH + y0 + 1;
        g_f2T[part][bin * 2][b] = r1;
        g_f2T[part][bin * 2 + 1][b] = i1;
    }
}

// ============================================================
// Sum partials: featT = sum over EPARTS (coalesced)
// ============================================================
__global__ __launch_bounds__(256) void sumfeat_kernel() {
    int t = blockIdx.x * 256 + threadIdx.x;
    const float* f0 = &g_f2T[0][0][0];
    float a = f0[t] + f0[t + NUFT_DIM * NB] + f0[t + 2 * NUFT_DIM * NB]
            + f0[t + 3 * NUFT_DIM * NB];
    (&g_featT[0][0])[t] = a;
}

// ============================================================
// GEMM1: split-K S1=64, KC1=66 (padded to 68), depth-2 W prefetch
// block 128: lane -> j-quad, warp -> m-octet; grid (8, 64)
// ============================================================
__global__ __launch_bounds__(128) void gemm1_kernel(const float* __restrict__ W1) {
    __shared__ float sh[KC1P * 32];
    int lane = threadIdx.x & 31, mq = threadIdx.x >> 5;
    int s = blockIdx.y;
    int j = (blockIdx.x * 32 + lane) * 4;
    int k0 = s * KC1;

    {
        const float4* s4 = (const float4*)&g_featT[k0][0];
        float4* d4 = (float4*)sh;
        for (int i = threadIdx.x; i < (KC1 * 32) / 4; i += 128) d4[i] = s4[i];
        if (threadIdx.x < 16)
            d4[(KC1 * 32) / 4 + threadIdx.x] = make_float4(0.f, 0.f, 0.f, 0.f);
    }
    __syncthreads();

    ull acc[16];
    #pragma unroll
    for (int q = 0; q < 16; q++) acc[q] = 0ull;

    const float4* wp = (const float4*)(W1 + (size_t)k0 * HID + j);
    const int ws = HID / 4;

    float4 A[4], B[4];
    #pragma unroll
    for (int u = 0; u < 4; u++) { int kk = u;     A[u] = wp[(size_t)kk * ws]; }
    #pragma unroll
    for (int u = 0; u < 4; u++) { int kk = 4 + u; B[u] = wp[(size_t)kk * ws]; }

    #pragma unroll 1
    for (int kb = 0; kb < KC1P; kb += 4) {
        float4 Cn[4];
        bool pf = (kb + 8) < KC1P;
        if (pf) {
            #pragma unroll
            for (int u = 0; u < 4; u++) {
                int kk = kb + 8 + u; if (kk >= KC1) kk = KC1 - 1;  // clamp (f=0 rows)
                Cn[u] = wp[(size_t)kk * ws];
            }
        }
        #pragma unroll
        for (int u = 0; u < 4; u++) {
            int k = kb + u;
            ull w0 = pack2(A[u].x), w1 = pack2(A[u].y);
            ull w2 = pack2(A[u].z), w3 = pack2(A[u].w);
            ulonglong2 fa = *(const ulonglong2*)(sh + k * 32 + mq * 8);
            ulonglong2 fb = *(const ulonglong2*)(sh + k * 32 + mq * 8 + 4);
            FMA2(acc[0],  fa.x, w0); FMA2(acc[1],  fa.x, w1);
            FMA2(acc[2],  fa.x, w2); FMA2(acc[3],  fa.x, w3);
            FMA2(acc[4],  fa.y, w0); FMA2(acc[5],  fa.y, w1);
            FMA2(acc[6],  fa.y, w2); FMA2(acc[7],  fa.y, w3);
            FMA2(acc[8],  fb.x, w0); FMA2(acc[9],  fb.x, w1);
            FMA2(acc[10], fb.x, w2); FMA2(acc[11], fb.x, w3);
            FMA2(acc[12], fb.y, w0); FMA2(acc[13], fb.y, w1);
            FMA2(acc[14], fb.y, w2); FMA2(acc[15], fb.y, w3);
        }
        #pragma unroll
        for (int u = 0; u < 4; u++) { A[u] = B[u]; if (pf) B[u] = Cn[u]; }
    }

    #pragma unroll
    for (int p = 0; p < 4; p++) {
        float lo0, hi0, lo1, hi1, lo2, hi2, lo3, hi3;
        unpack2(acc[p * 4 + 0], lo0, hi0);
        unpack2(acc[p * 4 + 1], lo1, hi1);
        unpack2(acc[p * 4 + 2], lo2, hi2);
        unpack2(acc[p * 4 + 3], lo3, hi3);
        int m0 = mq * 8 + 2 * p;
        *(float4*)(&g_p1[s][m0][j])     = make_float4(lo0, lo1, lo2, lo3);
        *(float4*)(&g_p1[s][m0 + 1][j]) = make_float4(hi0, hi1, hi2, hi3);
    }
}

// ============================================================
// epi1: 256 blocks x 128 thr; 4 warp-groups each sum 16 partials,
// smem combine, bias + relu, write transposed hT
// ============================================================
__global__ __launch_bounds__(128) void epi1_kernel(const float* __restrict__ b1) {
    __shared__ float4 red[4][32];
    int p = threadIdx.x & 31, sg = threadIdx.x >> 5;
    int gp = blockIdx.x * 32 + p;            // 0..8191
    int m = gp >> 8, j = (gp & 255) * 4;
    float4 a = make_float4(0.f, 0.f, 0.f, 0.f);
    #pragma unroll
    for (int s = 0; s < 16; s++) {
        float4 q = *(const float4*)(&g_p1[sg * 16 + s][m][j]);
        a.x += q.x; a.y += q.y; a.z += q.z; a.w += q.w;
    }
    red[sg][p] = a;
    __syncthreads();
    if (sg == 0) {
        float4 r0 = red[0][p], r1 = red[1][p], r2 = red[2][p], r3 = red[3][p];
        float4 bb = *(const float4*)(b1 + j);
        float ox = fmaxf(bb.x + r0.x + r1.x + r2.x + r3.x, 0.f);
        float oy = fmaxf(bb.y + r0.y + r1.y + r2.y + r3.y, 0.f);
        float oz = fmaxf(bb.z + r0.z + r1.z + r2.z + r3.z, 0.f);
        float ow = fmaxf(bb.w + r0.w + r1.w + r2.w + r3.w, 0.f);
        g_hT[j][m] = ox; g_hT[j + 1][m] = oy;
        g_hT[j + 2][m] = oz; g_hT[j + 3][m] = ow;
    }
}

// ============================================================
// GEMM2: split-K S2=64, KC2=16, depth-2 prefetch; grid (4, 64)
// ============================================================
__global__ __launch_bounds__(128) void gemm2_kernel(const float* __restrict__ W2) {
    __shared__ float sh[KC2 * 32];
    int lane = threadIdx.x & 31, mq = threadIdx.x >> 5;
    int s = blockIdx.y;
    int j = (blockIdx.x * 32 + lane) * 4;
    int k0 = s * KC2;

    {
        const float4* s4 = (const float4*)&g_hT[k0][0];
        float4* d4 = (float4*)sh;
        d4[threadIdx.x] = s4[threadIdx.x];   // 128 float4 = 16*32 floats
    }
    __syncthreads();

    ull acc[16];
    #pragma unroll
    for (int q = 0; q < 16; q++) acc[q] = 0ull;

    const float4* wp = (const float4*)(W2 + (size_t)k0 * OUTD + j);
    const int ws = OUTD / 4;

    float4 A[4], B[4];
    #pragma unroll
    for (int u = 0; u < 4; u++) A[u] = wp[(size_t)u * ws];
    #pragma unroll
    for (int u = 0; u < 4; u++) B[u] = wp[(size_t)(4 + u) * ws];

    #pragma unroll 1
    for (int kb = 0; kb < KC2; kb += 4) {
        float4 Cn[4];
        bool pf = (kb + 8) < KC2;
        if (pf) {
            #pragma unroll
            for (int u = 0; u < 4; u++) Cn[u] = wp[(size_t)(kb + 8 + u) * ws];
        }
        #pragma unroll
        for (int u = 0; u < 4; u++) {
            int k = kb + u;
            ull w0 = pack2(A[u].x), w1 = pack2(A[u].y);
            ull w2 = pack2(A[u].z), w3 = pack2(A[u].w);
            ulonglong2 fa = *(const ulonglong2*)(sh + k * 32 + mq * 8);
            ulonglong2 fb = *(const ulonglong2*)(sh + k * 32 + mq * 8 + 4);
            FMA2(acc[0],  fa.x, w0); FMA2(acc[1],  fa.x, w1);
            FMA2(acc[2],  fa.x, w2); FMA2(acc[3],  fa.x, w3);
            FMA2(acc[4],  fa.y, w0); FMA2(acc[5],  fa.y, w1);
            FMA2(acc[6],  fa.y, w2); FMA2(acc[7],  fa.y, w3);
            FMA2(acc[8],  fb.x, w0); FMA2(acc[9],  fb.x, w1);
            FMA2(acc[10], fb.x, w2); FMA2(acc[11], fb.x, w3);
            FMA2(acc[12], fb.y, w0); FMA2(acc[13], fb.y, w1);
            FMA2(acc[14], fb.y, w2); FMA2(acc[15], fb.y, w3);
        }
        #pragma unroll
        for (int u = 0; u < 4; u++) { A[u] = B[u]; if (pf) B[u] = Cn[u]; }
    }

    #pragma unroll
    for (int p = 0; p < 4; p++) {
        float lo0, hi0, lo1, hi1, lo2, hi2, lo3, hi3;
        unpack2(acc[p * 4 + 0], lo0, hi0);
        unpack2(acc[p * 4 + 1], lo1, hi1);
        unpack2(acc[p * 4 + 2], lo2, hi2);
        unpack2(acc[p * 4 + 3], lo3, hi3);
        int m0 = mq * 8 + 2 * p;
        *(float4*)(&g_p2[s][m0][j])     = make_float4(lo0, lo1, lo2, lo3);
        *(float4*)(&g_p2[s][m0 + 1][j]) = make_float4(hi0, hi1, hi2, hi3);
    }
}

// ============================================================
// epi2: 128 blocks x 128 thr, same 4x16 s-split + smem combine
// ============================================================
__global__ __launch_bounds__(128) void epi2_kernel(const float* __restrict__ b2,
                                                   float* __restrict__ out) {
    __shared__ float4 red[4][32];
    int p = threadIdx.x & 31, sg = threadIdx.x >> 5;
    int gp = blockIdx.x * 32 + p;            // 0..4095
    int m = gp >> 7, j = (gp & 127) * 4;
    float4 a = make_float4(0.f, 0.f, 0.f, 0.f);
    #pragma unroll
    for (int s = 0; s < 16; s++) {
        float4 q = *(const float4*)(&g_p2[sg * 16 + s][m][j]);
        a.x += q.x; a.y += q.y; a.z += q.z; a.w += q.w;
    }
    red[sg][p] = a;
    __syncthreads();
    if (sg == 0) {
        float4 r0 = red[0][p], r1 = red[1][p], r2 = red[2][p], r3 = red[3][p];
        float4 bb = *(const float4*)(b2 + j);
        float4 o;
        o.x = bb.x + r0.x + r1.x + r2.x + r3.x;
        o.y = bb.y + r0.y + r1.y + r2.y + r3.y;
        o.z = bb.z + r0.z + r1.z + r2.z + r3.z;
        o.w = bb.w + r0.w + r1.w + r2.w + r3.w;
        *(float4*)(out + m * OUTD + j) = o;
    }
}

// ============================================================
extern "C" void kernel_launch(void* const* d_in, const int* in_sizes, int n_in,
                              void* d_out, int out_size) {
    const float* P  = (const float*)d_in[0];
    const float* W1 = (const float*)d_in[1];
    const float* b1 = (const float*)d_in[2];
    const float* W2 = (const float*)d_in[3];
    const float* b2 = (const float*)d_in[4];
    float* out = (float*)d_out;

    pass1_kernel<<<(NB * NV * P1K + 255) / 256, 256>>>(P);
    pass2_kernel<<<dim3(FX * YQ / 128, NB, EPARTS), 128>>>();
    sumfeat_kernel<<<NUFT_DIM * NB / 256, 256>>>();
    gemm1_kernel<<<dim3(HID / 128, S1), 128>>>(W1);
    epi1_kernel<<<NB * HID / 4 / 32, 128>>>(b1);
    gemm2_kernel<<<dim3(OUTD / 128, S2), 128>>>(W2);
    epi2_kernel<<<NB * OUTD / 4 / 32, 128>>>(b2, out);
}